// round 5
// baseline (speedup 1.0000x reference)
#include <cuda_runtime.h>

// Problem constants (fixed by the dataset)
#define PB   2      // batch
#define PN   2048   // atoms
#define PM   64     // neighbors
#define PF   128    // features
#define PH1  64
#define PH2  64

#define NW   8      // warps per MLP block
#define APW  2      // atoms per warp
#define APB  (NW * APW)   // atoms per block = 16

// Scratch (allocation-free rule: __device__ globals)
__device__ float g_grad[PB * PN * PF];   // dEi/dx per atom, 4 MB (L2-resident)
__device__ float g_Ei[PB * PN];          // per-atom energies

// ---------------------------------------------------------------------------
// Kernel 1: warp-private MLP fwd + analytic input-gradient bwd.
// Each warp processes APW atoms; lane l owns outputs j=l and j=l+32.
// Weights in smem with skew [row][(col+row)&mask] -> conflict-free for both
// row-major (forward) and column-major (backward) reads.
// ---------------------------------------------------------------------------
__global__ void __launch_bounds__(NW * 32) mlp_kernel(
    const float* __restrict__ image,
    const float* __restrict__ W0,     // [H1, F]
    const float* __restrict__ W1,     // [H2, H1]
    const float* __restrict__ Wout)   // [1, H2]
{
    extern __shared__ float dyn[];
    float* sW0  = dyn;                 // 8192 floats, skewed [j][(f+j)&127]
    float* sW1  = sW0 + PH1 * PF;      // 4096 floats, skewed [k][(j+k)&63]
    float* sX   = sW1 + PH2 * PH1;     // NW*APW*PF floats, plain [at][f]
    float* sBuf = sX + NW * APW * PF;  // NW*APW*PH1 floats, plain [at][j]
    float* sWo  = sBuf + NW * APW * PH1; // 64 floats

    const int tid = threadIdx.x;
    const int w   = tid >> 5;
    const int l   = tid & 31;

    // ---- stage weights (skewed) ----
    for (int i = tid; i < PH1 * PF; i += NW * 32) {
        const int j = i >> 7, f = i & 127;
        sW0[(j << 7) + ((f + j) & 127)] = W0[i];
    }
    for (int i = tid; i < PH2 * PH1; i += NW * 32) {
        const int k = i >> 6, j = i & 63;
        sW1[(k << 6) + ((j + k) & 63)] = W1[i];
    }
    if (tid < PH2) sWo[tid] = Wout[tid];
    __syncthreads();

    const int a0 = blockIdx.x * APB + w * APW;
    float* wX = sX + w * (APW * PF);
    float* wB = sBuf + w * (APW * PH1);

    // ---- stage x for APW atoms: contiguous float4, conflict-free ----
    {
        const float4* src = (const float4*)(image + (size_t)a0 * PF);
        float4* dst = (float4*)wX;
        #pragma unroll
        for (int it = 0; it < APW; it++) dst[it * 32 + l] = src[it * 32 + l];
    }
    __syncwarp();

    // ---- L0 forward: h0[j] = sigmoid(sum_f W0[j,f] x[f]), j = l, l+32 ----
    float h0v[2][APW];
    {
        float acc[2][APW];
        #pragma unroll
        for (int h = 0; h < 2; h++)
            #pragma unroll
            for (int at = 0; at < APW; at++) acc[h][at] = 0.f;

        #pragma unroll 4
        for (int f = 0; f < PF; f += 4) {
            float4 xv[APW];
            #pragma unroll
            for (int at = 0; at < APW; at++)
                xv[at] = *(const float4*)(wX + at * PF + f);
            #pragma unroll
            for (int ff = 0; ff < 4; ff++) {
                const float wa = sW0[(l << 7) + ((f + ff + l) & 127)];
                const float wb = sW0[((l + 32) << 7) + ((f + ff + l + 32) & 127)];
                #pragma unroll
                for (int at = 0; at < APW; at++) {
                    const float xe = ((const float*)&xv[at])[ff];
                    acc[0][at] += wa * xe;
                    acc[1][at] += wb * xe;
                }
            }
        }
        #pragma unroll
        for (int h = 0; h < 2; h++)
            #pragma unroll
            for (int at = 0; at < APW; at++)
                h0v[h][at] = 1.f / (1.f + __expf(-acc[h][at]));
    }
    #pragma unroll
    for (int at = 0; at < APW; at++) {
        wB[at * PH1 + l]      = h0v[0][at];
        wB[at * PH1 + l + 32] = h0v[1][at];
    }
    __syncwarp();

    // ---- L1 forward: h1[k] = sigmoid(sum_j W1[k,j] h0[j]), k = l, l+32 ----
    float h1v[2][APW];
    {
        float acc[2][APW];
        #pragma unroll
        for (int h = 0; h < 2; h++)
            #pragma unroll
            for (int at = 0; at < APW; at++) acc[h][at] = 0.f;

        #pragma unroll 4
        for (int j = 0; j < PH1; j += 4) {
            float4 hv[APW];
            #pragma unroll
            for (int at = 0; at < APW; at++)
                hv[at] = *(const float4*)(wB + at * PH1 + j);
            #pragma unroll
            for (int ff = 0; ff < 4; ff++) {
                const float wa = sW1[(l << 6) + ((j + ff + l) & 63)];
                const float wb = sW1[((l + 32) << 6) + ((j + ff + l + 32) & 63)];
                #pragma unroll
                for (int at = 0; at < APW; at++) {
                    const float he = ((const float*)&hv[at])[ff];
                    acc[0][at] += wa * he;
                    acc[1][at] += wb * he;
                }
            }
        }
        #pragma unroll
        for (int h = 0; h < 2; h++)
            #pragma unroll
            for (int at = 0; at < APW; at++)
                h1v[h][at] = 1.f / (1.f + __expf(-acc[h][at]));
    }

    // ---- Ei = sum_k h1[k]*Wout[k] (deterministic warp shuffle reduce) ----
    const float wo0 = sWo[l], wo1 = sWo[l + 32];
    #pragma unroll
    for (int at = 0; at < APW; at++) {
        float v = h1v[0][at] * wo0 + h1v[1][at] * wo1;
        #pragma unroll
        for (int o = 16; o; o >>= 1) v += __shfl_down_sync(0xffffffffu, v, o);
        if (l == 0) g_Ei[a0 + at] = v;
    }
    __syncwarp();   // everyone done reading h0 from wB

    // ---- t1 = h1*(1-h1)*Wout -> publish (overwrites h0 buffer) ----
    #pragma unroll
    for (int at = 0; at < APW; at++) {
        wB[at * PH1 + l]      = h1v[0][at] * (1.f - h1v[0][at]) * wo0;
        wB[at * PH1 + l + 32] = h1v[1][at] * (1.f - h1v[1][at]) * wo1;
    }
    __syncwarp();

    // ---- gH1[j] = sum_k t1[k]*W1[k,j]; t0 = h0*(1-h0)*gH1, j = l, l+32 ----
    float t0v[2][APW];
    {
        float acc[2][APW];
        #pragma unroll
        for (int h = 0; h < 2; h++)
            #pragma unroll
            for (int at = 0; at < APW; at++) acc[h][at] = 0.f;

        #pragma unroll 4
        for (int k = 0; k < PH2; k += 4) {
            float4 tv[APW];
            #pragma unroll
            for (int at = 0; at < APW; at++)
                tv[at] = *(const float4*)(wB + at * PH1 + k);
            #pragma unroll
            for (int kk = 0; kk < 4; kk++) {
                const float wa = sW1[((k + kk) << 6) + ((l + k + kk) & 63)];
                const float wb = sW1[((k + kk) << 6) + ((l + 32 + k + kk) & 63)];
                #pragma unroll
                for (int at = 0; at < APW; at++) {
                    const float te = ((const float*)&tv[at])[kk];
                    acc[0][at] += wa * te;
                    acc[1][at] += wb * te;
                }
            }
        }
        #pragma unroll
        for (int h = 0; h < 2; h++)
            #pragma unroll
            for (int at = 0; at < APW; at++)
                t0v[h][at] = h0v[h][at] * (1.f - h0v[h][at]) * acc[h][at];
    }
    __syncwarp();   // done reading t1

    // ---- publish t0 ----
    #pragma unroll
    for (int at = 0; at < APW; at++) {
        wB[at * PH1 + l]      = t0v[0][at];
        wB[at * PH1 + l + 32] = t0v[1][at];
    }
    __syncwarp();

    // ---- g[f] = sum_j t0[j]*W0[j,f], f = l + 32q ----
    {
        float acc[4][APW];
        #pragma unroll
        for (int q = 0; q < 4; q++)
            #pragma unroll
            for (int at = 0; at < APW; at++) acc[q][at] = 0.f;

        for (int j = 0; j < PH1; j += 4) {
            float4 tv[APW];
            #pragma unroll
            for (int at = 0; at < APW; at++)
                tv[at] = *(const float4*)(wB + at * PH1 + j);
            #pragma unroll
            for (int jj = 0; jj < 4; jj++) {
                #pragma unroll
                for (int q = 0; q < 4; q++) {
                    const float wv = sW0[((j + jj) << 7) + ((l + 32 * q + j + jj) & 127)];
                    #pragma unroll
                    for (int at = 0; at < APW; at++)
                        acc[q][at] += wv * ((const float*)&tv[at])[jj];
                }
            }
        }
        #pragma unroll
        for (int at = 0; at < APW; at++)
            #pragma unroll
            for (int q = 0; q < 4; q++)
                g_grad[(size_t)(a0 + at) * PF + l + 32 * q] = acc[q][at];
    }
}

// ---------------------------------------------------------------------------
// Kernel 2: deterministic Etot reduction (no float atomics)
// ---------------------------------------------------------------------------
__global__ void etot_kernel(float* __restrict__ out)
{
    const int b = blockIdx.x;
    const int tid = threadIdx.x;
    __shared__ float sm[256];
    float s = 0.f;
    for (int i = tid; i < PN; i += 256) s += g_Ei[b * PN + i];
    sm[tid] = s;
    __syncthreads();
    #pragma unroll
    for (int o = 128; o; o >>= 1) {
        if (tid < o) sm[tid] += sm[tid + o];
        __syncthreads();
    }
    if (tid == 0) out[b] = sm[0];
}

// ---------------------------------------------------------------------------
// Kernel 3: force[b,n,c] = 1e10 * sum_{m,f} mask * g[b, nei-1, f] * dfeat[b,n,m,f,c]
// Gathered g tile staged in smem (zero rows for masked neighbors); dfeat
// streamed with pure linear float4 loads (512 contiguous B per warp instr =
// 4 L1 wavefronts, the minimum). (m,f,c) recovered arithmetically per float4.
// ---------------------------------------------------------------------------
__global__ void __launch_bounds__(128) force_kernel(
    const float* __restrict__ dfeat,
    const int*   __restrict__ neighbor,
    float*       __restrict__ out)     // out[0..1]=Etot, force at out+2
{
    const int bn  = blockIdx.x;        // 0 .. B*N-1
    const int b   = bn >> 11;          // / PN
    const int tid = threadIdx.x;

    __shared__ float gs[PM * PF];      // 32 KB gathered-g tile
    __shared__ int   sidx[PM];
    __shared__ float sred[4][3];

    if (tid < PM) sidx[tid] = neighbor[bn * PM + tid];
    __syncthreads();

    const float* grow = g_grad + (size_t)b * PN * PF;
    #pragma unroll
    for (int i = tid; i < PM * PF; i += 128) {
        const int m = i >> 7, f = i & 127;
        const int nv = sidx[m];
        gs[i] = (nv > 0) ? grow[(size_t)(nv - 1) * PF + f] : 0.f;
    }
    __syncthreads();

    // 98304 B per block = 6144 float4; 48 per thread, fully coalesced.
    const float4* df = (const float4*)(dfeat + (size_t)bn * (PM * PF * 3));
    float ax = 0.f, ay = 0.f, az = 0.f;

    #pragma unroll 4
    for (int k = 0; k < 48; k++) {
        const int q = k * 128 + tid;       // float4 index within block tile
        const float4 v = df[q];
        const int m  = q / 96;             // 96 float4 per m-row (384 floats)
        const int r  = (q - m * 96) * 4;   // element offset within row, 0..380
        const int f0 = r / 3;
        const int u  = r - f0 * 3;         // phase 0/1/2
        const float* gr = gs + (m << 7);
        const float ga = gr[f0];
        const float gb2 = gr[f0 + 1];
        if (u == 0) {
            ax += v.x * ga; ay += v.y * ga; az += v.z * ga; ax += v.w * gb2;
        } else if (u == 1) {
            ay += v.x * ga; az += v.y * ga; ax += v.z * gb2; ay += v.w * gb2;
        } else {
            az += v.x * ga; ax += v.y * gb2; ay += v.z * gb2; az += v.w * gb2;
        }
    }

    // reduce 128 threads -> 3 floats
    #pragma unroll
    for (int o = 16; o; o >>= 1) {
        ax += __shfl_down_sync(0xffffffffu, ax, o);
        ay += __shfl_down_sync(0xffffffffu, ay, o);
        az += __shfl_down_sync(0xffffffffu, az, o);
    }
    const int w = tid >> 5, l = tid & 31;
    if (l == 0) { sred[w][0] = ax; sred[w][1] = ay; sred[w][2] = az; }
    __syncthreads();
    if (tid < 3) {
        const float v = sred[0][tid] + sred[1][tid] + sred[2][tid] + sred[3][tid];
        out[2 + bn * 3 + tid] = v * 1e10f;
    }
}

// ---------------------------------------------------------------------------
extern "C" void kernel_launch(void* const* d_in, const int* in_sizes, int n_in,
                              void* d_out, int out_size)
{
    const float* image    = (const float*)d_in[0];
    const float* dfeat    = (const float*)d_in[1];
    const int*   neighbor = (const int*)  d_in[2];
    // d_in[3] Egroup_weight, d_in[4] divider: unused by the reference math
    const float* W0       = (const float*)d_in[5];
    const float* W1       = (const float*)d_in[6];
    const float* Wout     = (const float*)d_in[7];
    float* out = (float*)d_out;

    const int smem_bytes = (PH1 * PF + PH2 * PH1 + NW * APW * PF + NW * APW * PH1 + PH2) * 4;
    cudaFuncSetAttribute(mlp_kernel, cudaFuncAttributeMaxDynamicSharedMemorySize, smem_bytes);

    mlp_kernel<<<(PB * PN) / APB, NW * 32, smem_bytes>>>(image, W0, W1, Wout);
    etot_kernel<<<PB, 256>>>(out);
    force_kernel<<<PB * PN, 128>>>(dfeat, neighbor, out);
}

// round 7
// speedup vs baseline: 2.3361x; 2.3361x over previous
#include <cuda_runtime.h>

// Problem constants (fixed by the dataset)
#define PB   2      // batch
#define PN   2048   // atoms
#define PM   64     // neighbors
#define PF   128    // features
#define PH1  64
#define PH2  64

#define NW   4      // warps per MLP block
#define APW  4      // atoms per warp
#define APB  (NW * APW)   // atoms per block = 16

// Padded weight row strides (conflict-free banks without index math)
#define W0S  129    // (129*l + f) % 32 == (l+f)%32 -> distinct per lane
#define W1S  65

// Scratch (allocation-free rule: __device__ globals)
__device__ float g_grad[PB * PN * PF];   // dEi/dx per atom, 4 MB (L2-resident)
__device__ float g_Ei[PB * PN];          // per-atom energies

// ---------------------------------------------------------------------------
// Kernel 1: warp-private MLP fwd + analytic input-gradient bwd.
// APW=4 atoms per warp amortizes weight LDS; padded rows give conflict-free
// access for BOTH row-major (fwd) and column-major (bwd) reads with plain
// pointer arithmetic (no skew ALU).
// ---------------------------------------------------------------------------
__global__ void __launch_bounds__(NW * 32) mlp_kernel(
    const float* __restrict__ image,
    const float* __restrict__ W0,     // [H1, F]
    const float* __restrict__ W1,     // [H2, H1]
    const float* __restrict__ Wout)   // [1, H2]
{
    extern __shared__ float dyn[];
    float* sW0  = dyn;                     // 64*129 floats, padded rows
    float* sW1  = sW0 + PH1 * W0S;         // 64*65 floats, padded rows
    float* sX   = sW1 + PH2 * W1S;         // NW*APW*PF, plain [at][f]
    float* sBuf = sX + NW * APW * PF;      // NW*APW*PH1, plain [at][j]
    float* sWo  = sBuf + NW * APW * PH1;   // 64

    const int tid = threadIdx.x;
    const int w   = tid >> 5;
    const int l   = tid & 31;

    // ---- stage weights (padded) ----
    for (int i = tid; i < PH1 * PF; i += NW * 32)
        sW0[(i >> 7) * W0S + (i & 127)] = W0[i];
    for (int i = tid; i < PH2 * PH1; i += NW * 32)
        sW1[(i >> 6) * W1S + (i & 63)] = W1[i];
    if (tid < PH2) sWo[tid] = Wout[tid];
    __syncthreads();

    const int a0 = blockIdx.x * APB + w * APW;
    float* wX = sX + w * (APW * PF);
    float* wB = sBuf + w * (APW * PH1);

    // ---- stage x for APW atoms: contiguous float4, conflict-free ----
    {
        const float4* src = (const float4*)(image + (size_t)a0 * PF);
        float4* dst = (float4*)wX;
        #pragma unroll
        for (int it = 0; it < APW; it++) dst[it * 32 + l] = src[it * 32 + l];
    }
    __syncwarp();

    const float* w0a = sW0 + l * W0S;          // row l
    const float* w0b = sW0 + (l + 32) * W0S;   // row l+32
    const float* w1a = sW1 + l * W1S;
    const float* w1b = sW1 + (l + 32) * W1S;

    // ---- L0 forward: h0[j] = sigmoid(sum_f W0[j,f] x[f]), j = l, l+32 ----
    float h0v[2][APW];
    {
        float acc[2][APW];
        #pragma unroll
        for (int h = 0; h < 2; h++)
            #pragma unroll
            for (int at = 0; at < APW; at++) acc[h][at] = 0.f;

        #pragma unroll 4
        for (int f = 0; f < PF; f += 4) {
            float4 xv[APW];
            #pragma unroll
            for (int at = 0; at < APW; at++)
                xv[at] = *(const float4*)(wX + at * PF + f);
            #pragma unroll
            for (int ff = 0; ff < 4; ff++) {
                const float wa = w0a[f + ff];
                const float wb = w0b[f + ff];
                #pragma unroll
                for (int at = 0; at < APW; at++) {
                    const float xe = ((const float*)&xv[at])[ff];
                    acc[0][at] += wa * xe;
                    acc[1][at] += wb * xe;
                }
            }
        }
        #pragma unroll
        for (int h = 0; h < 2; h++)
            #pragma unroll
            for (int at = 0; at < APW; at++)
                h0v[h][at] = 1.f / (1.f + __expf(-acc[h][at]));
    }
    #pragma unroll
    for (int at = 0; at < APW; at++) {
        wB[at * PH1 + l]      = h0v[0][at];
        wB[at * PH1 + l + 32] = h0v[1][at];
    }
    __syncwarp();

    // ---- L1 forward: h1[k] = sigmoid(sum_j W1[k,j] h0[j]), k = l, l+32 ----
    float h1v[2][APW];
    {
        float acc[2][APW];
        #pragma unroll
        for (int h = 0; h < 2; h++)
            #pragma unroll
            for (int at = 0; at < APW; at++) acc[h][at] = 0.f;

        #pragma unroll 4
        for (int j = 0; j < PH1; j += 4) {
            float4 hv[APW];
            #pragma unroll
            for (int at = 0; at < APW; at++)
                hv[at] = *(const float4*)(wB + at * PH1 + j);
            #pragma unroll
            for (int ff = 0; ff < 4; ff++) {
                const float wa = w1a[j + ff];
                const float wb = w1b[j + ff];
                #pragma unroll
                for (int at = 0; at < APW; at++) {
                    const float he = ((const float*)&hv[at])[ff];
                    acc[0][at] += wa * he;
                    acc[1][at] += wb * he;
                }
            }
        }
        #pragma unroll
        for (int h = 0; h < 2; h++)
            #pragma unroll
            for (int at = 0; at < APW; at++)
                h1v[h][at] = 1.f / (1.f + __expf(-acc[h][at]));
    }

    // ---- Ei = sum_k h1[k]*Wout[k] (deterministic warp shuffle reduce) ----
    const float wo0 = sWo[l], wo1 = sWo[l + 32];
    #pragma unroll
    for (int at = 0; at < APW; at++) {
        float v = h1v[0][at] * wo0 + h1v[1][at] * wo1;
        #pragma unroll
        for (int o = 16; o; o >>= 1) v += __shfl_down_sync(0xffffffffu, v, o);
        if (l == 0) g_Ei[a0 + at] = v;
    }
    __syncwarp();   // everyone done reading h0 from wB

    // ---- t1 = h1*(1-h1)*Wout -> publish (overwrites h0 buffer) ----
    #pragma unroll
    for (int at = 0; at < APW; at++) {
        wB[at * PH1 + l]      = h1v[0][at] * (1.f - h1v[0][at]) * wo0;
        wB[at * PH1 + l + 32] = h1v[1][at] * (1.f - h1v[1][at]) * wo1;
    }
    __syncwarp();

    // ---- gH1[j] = sum_k t1[k]*W1[k,j]; t0 = h0*(1-h0)*gH1, j = l, l+32 ----
    float t0v[2][APW];
    {
        float acc[2][APW];
        #pragma unroll
        for (int h = 0; h < 2; h++)
            #pragma unroll
            for (int at = 0; at < APW; at++) acc[h][at] = 0.f;

        #pragma unroll 4
        for (int k = 0; k < PH2; k += 4) {
            float4 tv[APW];
            #pragma unroll
            for (int at = 0; at < APW; at++)
                tv[at] = *(const float4*)(wB + at * PH1 + k);
            #pragma unroll
            for (int kk = 0; kk < 4; kk++) {
                // column read of padded W1: banks (k*65 + l) % 32 distinct
                const float wa = sW1[(k + kk) * W1S + l];
                const float wb = sW1[(k + kk) * W1S + l + 32];
                #pragma unroll
                for (int at = 0; at < APW; at++) {
                    const float te = ((const float*)&tv[at])[kk];
                    acc[0][at] += wa * te;
                    acc[1][at] += wb * te;
                }
            }
        }
        #pragma unroll
        for (int h = 0; h < 2; h++)
            #pragma unroll
            for (int at = 0; at < APW; at++)
                t0v[h][at] = h0v[h][at] * (1.f - h0v[h][at]) * acc[h][at];
    }
    __syncwarp();   // done reading t1

    // ---- publish t0 ----
    #pragma unroll
    for (int at = 0; at < APW; at++) {
        wB[at * PH1 + l]      = t0v[0][at];
        wB[at * PH1 + l + 32] = t0v[1][at];
    }
    __syncwarp();

    // ---- g[f] = sum_j t0[j]*W0[j,f], f = l + 32q ----
    {
        float acc[4][APW];
        #pragma unroll
        for (int q = 0; q < 4; q++)
            #pragma unroll
            for (int at = 0; at < APW; at++) acc[q][at] = 0.f;

        for (int j = 0; j < PH1; j += 4) {
            float4 tv[APW];
            #pragma unroll
            for (int at = 0; at < APW; at++)
                tv[at] = *(const float4*)(wB + at * PH1 + j);
            #pragma unroll
            for (int jj = 0; jj < 4; jj++) {
                const float* wrow = sW0 + (j + jj) * W0S + l;
                #pragma unroll
                for (int q = 0; q < 4; q++) {
                    const float wv = wrow[32 * q];   // banks (j + l) % 32 distinct
                    #pragma unroll
                    for (int at = 0; at < APW; at++)
                        acc[q][at] += wv * ((const float*)&tv[at])[jj];
                }
            }
        }
        #pragma unroll
        for (int at = 0; at < APW; at++)
            #pragma unroll
            for (int q = 0; q < 4; q++)
                g_grad[(size_t)(a0 + at) * PF + l + 32 * q] = acc[q][at];
    }
}

// ---------------------------------------------------------------------------
// Kernel 2: deterministic Etot reduction (no float atomics)
// ---------------------------------------------------------------------------
__global__ void etot_kernel(float* __restrict__ out)
{
    const int b = blockIdx.x;
    const int tid = threadIdx.x;
    __shared__ float sm[256];
    float s = 0.f;
    for (int i = tid; i < PN; i += 256) s += g_Ei[b * PN + i];
    sm[tid] = s;
    __syncthreads();
    #pragma unroll
    for (int o = 128; o; o >>= 1) {
        if (tid < o) sm[tid] += sm[tid + o];
        __syncthreads();
    }
    if (tid == 0) out[b] = sm[0];
}

// ---------------------------------------------------------------------------
// Kernel 3: force via double-buffered smem pipeline.
// Per chunk (8 m-rows): dfeat (12 KB) and the 8 gathered g-rows (4 KB) are
// prefetched into registers one chunk ahead (coalesced float4 LDG — minimum
// L1 wavefronts), staged to smem, and consumed with uniform, divergence-free
// scalar LDS: f = tid; dfeat banks stride 3 (coprime 32) -> conflict-free.
// One __syncthreads per chunk.
// ---------------------------------------------------------------------------
__global__ void __launch_bounds__(128) force_kernel(
    const float* __restrict__ dfeat,
    const int*   __restrict__ neighbor,
    float*       __restrict__ out)     // out[0..1]=Etot, force at out+2
{
    const int bn  = blockIdx.x;        // 0 .. B*N-1
    const int b   = bn >> 11;          // / PN
    const int tid = threadIdx.x;

    __shared__ float4 buf4[2][768];    // 2 x 12 KB dfeat chunks (8 rows x 384 f)
    __shared__ float4 gs4[2][256];     // 2 x 4 KB g chunks (8 rows x 128 f)
    __shared__ int    sidx[PM];
    __shared__ float  sred[4][3];

    if (tid < PM) sidx[tid] = neighbor[bn * PM + tid];
    __syncthreads();

    const float4* df4 = (const float4*)(dfeat + (size_t)bn * (PM * PF * 3));
    const float4* g4  = (const float4*)(g_grad + (size_t)b * PN * PF);

    float4 rd[6], rg[2];

    // ---- prologue: chunk 0 ----
    #pragma unroll
    for (int k = 0; k < 6; k++) rd[k] = df4[k * 128 + tid];
    #pragma unroll
    for (int k = 0; k < 2; k++) {
        const int q = k * 128 + tid;
        const int ml = q >> 5, c2 = q & 31;    // warp-uniform row, lane = col
        const int nv = sidx[ml];
        rg[k] = (nv > 0) ? g4[(size_t)(nv - 1) * 32 + c2]
                         : make_float4(0.f, 0.f, 0.f, 0.f);
    }
    #pragma unroll
    for (int k = 0; k < 6; k++) buf4[0][k * 128 + tid] = rd[k];
    #pragma unroll
    for (int k = 0; k < 2; k++) gs4[0][k * 128 + tid] = rg[k];
    __syncthreads();

    float ax = 0.f, ay = 0.f, az = 0.f;

    #pragma unroll
    for (int c = 0; c < 8; c++) {
        const int cur = c & 1;
        if (c < 7) {   // prefetch chunk c+1 into registers
            #pragma unroll
            for (int k = 0; k < 6; k++)
                rd[k] = df4[(c + 1) * 768 + k * 128 + tid];
            #pragma unroll
            for (int k = 0; k < 2; k++) {
                const int q = k * 128 + tid;
                const int ml = q >> 5, c2 = q & 31;
                const int nv = sidx[(c + 1) * 8 + ml];
                rg[k] = (nv > 0) ? g4[(size_t)(nv - 1) * 32 + c2]
                                 : make_float4(0.f, 0.f, 0.f, 0.f);
            }
        }

        // consume chunk c: uniform indexing, no divergence
        const float* bb = (const float*)buf4[cur];
        const float* gg = (const float*)gs4[cur];
        #pragma unroll
        for (int mm = 0; mm < 8; mm++) {
            const float gv = gg[mm * 128 + tid];          // banks tid%32
            const float* row = bb + mm * 384 + tid * 3;   // banks (3*tid)%32
            ax += gv * row[0];
            ay += gv * row[1];
            az += gv * row[2];
        }

        if (c < 7) {   // stage prefetched chunk into the other buffer
            #pragma unroll
            for (int k = 0; k < 6; k++) buf4[cur ^ 1][k * 128 + tid] = rd[k];
            #pragma unroll
            for (int k = 0; k < 2; k++) gs4[cur ^ 1][k * 128 + tid] = rg[k];
        }
        __syncthreads();
    }

    // reduce 128 threads -> 3 floats
    #pragma unroll
    for (int o = 16; o; o >>= 1) {
        ax += __shfl_down_sync(0xffffffffu, ax, o);
        ay += __shfl_down_sync(0xffffffffu, ay, o);
        az += __shfl_down_sync(0xffffffffu, az, o);
    }
    const int w = tid >> 5, l = tid & 31;
    if (l == 0) { sred[w][0] = ax; sred[w][1] = ay; sred[w][2] = az; }
    __syncthreads();
    if (tid < 3) {
        const float v = sred[0][tid] + sred[1][tid] + sred[2][tid] + sred[3][tid];
        out[2 + bn * 3 + tid] = v * 1e10f;
    }
}

// ---------------------------------------------------------------------------
extern "C" void kernel_launch(void* const* d_in, const int* in_sizes, int n_in,
                              void* d_out, int out_size)
{
    const float* image    = (const float*)d_in[0];
    const float* dfeat    = (const float*)d_in[1];
    const int*   neighbor = (const int*)  d_in[2];
    // d_in[3] Egroup_weight, d_in[4] divider: unused by the reference math
    const float* W0       = (const float*)d_in[5];
    const float* W1       = (const float*)d_in[6];
    const float* Wout     = (const float*)d_in[7];
    float* out = (float*)d_out;

    const int smem_bytes = (PH1 * W0S + PH2 * W1S + NW * APW * PF
                            + NW * APW * PH1 + PH2) * 4;
    cudaFuncSetAttribute(mlp_kernel, cudaFuncAttributeMaxDynamicSharedMemorySize, smem_bytes);

    mlp_kernel<<<(PB * PN) / APB, NW * 32, smem_bytes>>>(image, W0, W1, Wout);
    etot_kernel<<<PB, 256>>>(out);
    force_kernel<<<PB * PN, 128>>>(dfeat, neighbor, out);
}